// round 11
// baseline (speedup 1.0000x reference)
#include <cuda_runtime.h>
#include <cuda_bf16.h>
#include <stdint.h>

// Problem constants (fixed by the reference setup)
#define N_BATCH 8
#define C_CH    490     // OUTPUT_DIM * GROUP * GROUP = 10*49
#define H_DIM   64
#define W_DIM   64
#define R_ROIS  2000
#define D_OUT   10
#define G_GRP   7
#define G2_CNT  49      // 7*7
#define SPATIAL_SCALE 0.0625f

#define IHP      65     // H+1 rows in padded integral
#define P_STRIDE 68     // row stride: 16B-aligned rows (stride%4==0);
                        //  pass1 (adjacent t -> adjacent addr): conflict-free
                        //  pass2 LDS.128 (8-thread phases, banks 4(t+1)+{0..3}): conflict-free
#define PLANE_F  (IHP * P_STRIDE)   // 4420 floats = 17.68 KB

// Small scratch (L2-resident): packed bin bounds per (roi, g2), batch buckets.
__device__ uint32_t g_bounds[R_ROIS * G2_CNT];   // 392 KB
__device__ int      g_roi_sorted[R_ROIS];
__device__ int      g_batch_start[N_BATCH + 1];

// ---------------------------------------------------------------------------
// Prep (single launch): block 0 buckets ROIs by batch; other blocks compute
// packed bin bounds, concurrently.
// Bounds math: EXACT chain validated R8-R10 (rel_err 1.73e-6):
//   bh = roi_h * fl(1/7)  (reciprocal multiply, XLA-style)
//   boundaries = SEPARATE __fmul_rn + __fadd_rn (no FMA contraction)
// ---------------------------------------------------------------------------
__global__ void __launch_bounds__(256) prep_kernel(const float* __restrict__ rois) {
    const int tid = threadIdx.x;

    if (blockIdx.x == 0) {
        __shared__ int counts[N_BATCH];
        __shared__ int cursor[N_BATCH];
        if (tid < N_BATCH) counts[tid] = 0;
        __syncthreads();
        for (int i = tid; i < R_ROIS; i += 256) {
            int b = (int)rois[i * 5];
            atomicAdd(&counts[b], 1);
        }
        __syncthreads();
        if (tid == 0) {
            int acc = 0;
            for (int n = 0; n < N_BATCH; ++n) {
                g_batch_start[n] = acc;
                cursor[n] = acc;
                acc += counts[n];
            }
            g_batch_start[N_BATCH] = acc;
        }
        __syncthreads();
        for (int i = tid; i < R_ROIS; i += 256) {
            int b = (int)rois[i * 5];
            int pos = atomicAdd(&cursor[b], 1);
            g_roi_sorted[pos] = i;
        }
        return;
    }

    const int idx = (blockIdx.x - 1) * 256 + tid;
    if (idx >= R_ROIS * G2_CNT) return;

    const int r  = idx / G2_CNT;
    const int g2 = idx - r * G2_CNT;
    const int gh = g2 / G_GRP;
    const int gw = g2 - gh * G_GRP;

    const float* roi = rois + r * 5;

    const float rsw = __fmul_rn(rintf(roi[1]), SPATIAL_SCALE);
    const float rsh = __fmul_rn(rintf(roi[2]), SPATIAL_SCALE);
    const float rew = __fmul_rn(rintf(__fadd_rn(roi[3], 1.0f)), SPATIAL_SCALE);
    const float reh = __fmul_rn(rintf(__fadd_rn(roi[4], 1.0f)), SPATIAL_SCALE);

    const float roi_w = fmaxf(__fsub_rn(rew, rsw), 0.1f);
    const float roi_h = fmaxf(__fsub_rn(reh, rsh), 0.1f);

    const float INV7 = 1.0f / 7.0f;                  // fl(1/7), compile-time rn
    const float bw = __fmul_rn(roi_w, INV7);
    const float bh = __fmul_rn(roi_h, INV7);

    const float ghf  = (float)gh,  gwf  = (float)gw;
    const float gh1f = ghf + 1.0f, gw1f = gwf + 1.0f;

    float hs_f = floorf(__fadd_rn(rsh, __fmul_rn(ghf,  bh)));
    float he_f = ceilf (__fadd_rn(rsh, __fmul_rn(gh1f, bh)));
    float ws_f = floorf(__fadd_rn(rsw, __fmul_rn(gwf,  bw)));
    float we_f = ceilf (__fadd_rn(rsw, __fmul_rn(gw1f, bw)));

    hs_f = fminf(fmaxf(hs_f, 0.f), (float)H_DIM);
    he_f = fminf(fmaxf(he_f, 0.f), (float)H_DIM);
    ws_f = fminf(fmaxf(ws_f, 0.f), (float)W_DIM);
    we_f = fminf(fmaxf(we_f, 0.f), (float)W_DIM);

    g_bounds[idx] = (uint32_t)(int)hs_f
                  | ((uint32_t)(int)he_f << 8)
                  | ((uint32_t)(int)ws_f << 16)
                  | ((uint32_t)(int)we_f << 24);
}

// ---------------------------------------------------------------------------
// Fused kernel: ONE plane per 128-thread block, tuned for occupancy:
//   smem 17.68 KB + launch_bounds(128,12) => 12 blocks/SM, 75% occupancy
//   (R10's 2-plane version: 35 KB smem + 80 regs => only 6 blocks, 32% occ,
//    latency-bound at DRAM 27%).
// Scan keeps the reference's exact fp32 op order. Pass 2 uses float4 LDS/STS
// covering cols 0..63 (col 0 is the zero pad: s = 0+0 = 0 is exact, so the
// add chain is bit-identical), then col 64 scalar.
// ---------------------------------------------------------------------------
__global__ void __launch_bounds__(128, 12) fused_kernel(const float* __restrict__ feature,
                                                        float* __restrict__ out) {
    __shared__ float P[PLANE_F];

    const int plane = blockIdx.x;                 // 0 .. N*C-1
    const int n  = plane / C_CH;
    const int c  = plane - n * C_CH;
    const int g2 = c % G2_CNT;
    const int tid = threadIdx.x;

    const float* __restrict__ src = feature + (size_t)plane * (H_DIM * W_DIM);

    // Zero padding: row 0 cols 0..64, column 0 rows 0..64
    if (tid < IHP) {
        P[tid] = 0.f;
        P[tid * P_STRIDE] = 0.f;
    }

    // Vectorized interior load: 1024 float4, 8 per thread
    {
        const float4* __restrict__ src4 = (const float4*)src;
        #pragma unroll
        for (int i = tid; i < (H_DIM * W_DIM) / 4; i += 128) {
            const float4 v = src4[i];
            const int row  = i >> 4;              // (i*4)/64
            const int col0 = (i & 15) << 2;       // (i*4)%64
            float* p = P + (row + 1) * P_STRIDE + (col0 + 1);
            p[0] = v.x; p[1] = v.y; p[2] = v.z; p[3] = v.w;
        }
    }
    __syncthreads();

    // Pass 1: cumsum along H (axis=2). Thread t owns column t+1. Conflict-free.
    if (tid < W_DIM) {
        float s = 0.f;
        #pragma unroll
        for (int r = 1; r <= H_DIM; ++r) {
            s = __fadd_rn(s, P[r * P_STRIDE + (tid + 1)]);
            P[r * P_STRIDE + (tid + 1)] = s;
        }
    }
    __syncthreads();

    // Pass 2: cumsum along W (axis=3). Thread t owns row t+1.
    // float4 over cols 0..63 (col 0 = pad zero, exact), then col 64 scalar.
    if (tid < H_DIM) {
        float* rp = P + (tid + 1) * P_STRIDE;     // 16B-aligned (stride 68)
        float4* rp4 = (float4*)rp;
        float s = 0.f;
        #pragma unroll
        for (int q = 0; q < 16; ++q) {
            float4 v = rp4[q];
            s = __fadd_rn(s, v.x); v.x = s;
            s = __fadd_rn(s, v.y); v.y = s;
            s = __fadd_rn(s, v.z); v.z = s;
            s = __fadd_rn(s, v.w); v.w = s;
            rp4[q] = v;
        }
        s = __fadd_rn(s, rp[64]); rp[64] = s;
    }
    __syncthreads();

    // Pooling: one output per ROI of batch n from this plane.
    const int s_idx = g_batch_start[n];
    const int e_idx = g_batch_start[n + 1];

    for (int i = s_idx + tid; i < e_idx; i += 128) {
        const int r = g_roi_sorted[i];
        const uint32_t pk = g_bounds[r * G2_CNT + g2];
        const int hs = (int)(pk & 0xFF);
        const int he = (int)((pk >> 8) & 0xFF);
        const int ws = (int)((pk >> 16) & 0xFF);
        const int we = (int)(pk >> 24);

        const float a00 = P[he * P_STRIDE + we];
        const float a01 = P[hs * P_STRIDE + we];
        const float a10 = P[he * P_STRIDE + ws];
        const float a11 = P[hs * P_STRIDE + ws];

        // reference order: ((a - b) - c) + d, each step rn fp32
        const float sum = __fadd_rn(__fsub_rn(__fsub_rn(a00, a01), a10), a11);

        const int area = (he - hs) * (we - ws);
        const float area_f = fmaxf((float)area, 1.0f);
        out[(size_t)r * C_CH + c] = (area <= 0) ? 0.f : __fdiv_rn(sum, area_f);
    }
}

extern "C" void kernel_launch(void* const* d_in, const int* in_sizes, int n_in,
                              void* d_out, int out_size) {
    const float* feature = (const float*)d_in[0];   // (8, 490, 64, 64) fp32
    const float* rois    = (const float*)d_in[1];   // (2000, 5) fp32
    float* out = (float*)d_out;                     // (2000, 10, 7, 7) fp32

    const int bounds_blocks = (R_ROIS * G2_CNT + 255) / 256;   // 383
    prep_kernel<<<1 + bounds_blocks, 256>>>(rois);
    fused_kernel<<<N_BATCH * C_CH, 128>>>(feature, out);
}

// round 13
// speedup vs baseline: 1.0010x; 1.0010x over previous
#include <cuda_runtime.h>
#include <cuda_bf16.h>
#include <stdint.h>

// Problem constants (fixed by the reference setup)
#define N_BATCH 8
#define C_CH    490     // OUTPUT_DIM * GROUP * GROUP = 10*49
#define H_DIM   64
#define W_DIM   64
#define R_ROIS  2000
#define D_OUT   10
#define G_GRP   7
#define G2_CNT  49      // 7*7
#define SPATIAL_SCALE 0.0625f

#define IHP      65     // rows 0..64 of padded integral
#define P_STRIDE 67     // odd stride: conflict-free serial column/row walks
#define PLANE_F  (IHP * P_STRIDE)   // 4355 floats = 17.42 KB

// Small scratch (L2-resident): packed bin bounds per (roi, g2), batch buckets.
__device__ uint32_t g_bounds[R_ROIS * G2_CNT];   // 392 KB
__device__ int      g_roi_sorted[R_ROIS];
__device__ int      g_batch_start[N_BATCH + 1];

// ---------------------------------------------------------------------------
// Prep (single launch): block 0 buckets ROIs by batch; other blocks compute
// packed bin bounds, concurrently.
// Bounds math: EXACT chain validated R8-R11 (bit-critical, DO NOT TOUCH):
//   bh = roi_h * fl(1/7)  (reciprocal multiply, XLA-style)
//   boundaries = SEPARATE __fmul_rn + __fadd_rn (no FMA contraction)
// ---------------------------------------------------------------------------
__global__ void __launch_bounds__(256) prep_kernel(const float* __restrict__ rois) {
    const int tid = threadIdx.x;

    if (blockIdx.x == 0) {
        __shared__ int counts[N_BATCH];
        __shared__ int cursor[N_BATCH];
        if (tid < N_BATCH) counts[tid] = 0;
        __syncthreads();
        for (int i = tid; i < R_ROIS; i += 256) {
            int b = (int)rois[i * 5];
            atomicAdd(&counts[b], 1);
        }
        __syncthreads();
        if (tid == 0) {
            int acc = 0;
            for (int n = 0; n < N_BATCH; ++n) {
                g_batch_start[n] = acc;
                cursor[n] = acc;
                acc += counts[n];
            }
            g_batch_start[N_BATCH] = acc;
        }
        __syncthreads();
        for (int i = tid; i < R_ROIS; i += 256) {
            int b = (int)rois[i * 5];
            int pos = atomicAdd(&cursor[b], 1);
            g_roi_sorted[pos] = i;
        }
        return;
    }

    const int idx = (blockIdx.x - 1) * 256 + tid;
    if (idx >= R_ROIS * G2_CNT) return;

    const int r  = idx / G2_CNT;
    const int g2 = idx - r * G2_CNT;
    const int gh = g2 / G_GRP;
    const int gw = g2 - gh * G_GRP;

    const float* roi = rois + r * 5;

    const float rsw = __fmul_rn(rintf(roi[1]), SPATIAL_SCALE);
    const float rsh = __fmul_rn(rintf(roi[2]), SPATIAL_SCALE);
    const float rew = __fmul_rn(rintf(__fadd_rn(roi[3], 1.0f)), SPATIAL_SCALE);
    const float reh = __fmul_rn(rintf(__fadd_rn(roi[4], 1.0f)), SPATIAL_SCALE);

    const float roi_w = fmaxf(__fsub_rn(rew, rsw), 0.1f);
    const float roi_h = fmaxf(__fsub_rn(reh, rsh), 0.1f);

    const float INV7 = 1.0f / 7.0f;                  // fl(1/7), compile-time rn
    const float bw = __fmul_rn(roi_w, INV7);
    const float bh = __fmul_rn(roi_h, INV7);

    const float ghf  = (float)gh,  gwf  = (float)gw;
    const float gh1f = ghf + 1.0f, gw1f = gwf + 1.0f;

    float hs_f = floorf(__fadd_rn(rsh, __fmul_rn(ghf,  bh)));
    float he_f = ceilf (__fadd_rn(rsh, __fmul_rn(gh1f, bh)));
    float ws_f = floorf(__fadd_rn(rsw, __fmul_rn(gwf,  bw)));
    float we_f = ceilf (__fadd_rn(rsw, __fmul_rn(gw1f, bw)));

    hs_f = fminf(fmaxf(hs_f, 0.f), (float)H_DIM);
    he_f = fminf(fmaxf(he_f, 0.f), (float)H_DIM);
    ws_f = fminf(fmaxf(ws_f, 0.f), (float)W_DIM);
    we_f = fminf(fmaxf(we_f, 0.f), (float)W_DIM);

    g_bounds[idx] = (uint32_t)(int)hs_f
                  | ((uint32_t)(int)he_f << 8)
                  | ((uint32_t)(int)ws_f << 16)
                  | ((uint32_t)(int)we_f << 24);
}

// ---------------------------------------------------------------------------
// Fused kernel: 2 planes (d-pair, same g2 -> shared bounds) per 256-thread
// block. All 256 threads active in every phase:
//  - row scan: warp Kogge-Stone in registers, fed by coalesced float2 LDG
//    (raw tile never staged in smem), one STS pass of the scanned rows
//  - column scan: 2 threads/column segmented serial (chain 32) + parallel fixup
//  - pooling: one bounds load serves both planes (ILP-2)
// Sum association differs from the reference's sequential cumsum - allowed,
// bins are exact (R8-R11) and reassociation delta ~1e-5 << 1e-3 tolerance.
// smem 34.8 KB -> 6 blocks/SM -> 75% occupancy.
// ---------------------------------------------------------------------------
__global__ void __launch_bounds__(256) fused_kernel(const float* __restrict__ feature,
                                                    float* __restrict__ out) {
    __shared__ float P[2 * PLANE_F];

    const int bid = blockIdx.x;                   // 0 .. 1959
    const int n   = bid / (G2_CNT * (D_OUT / 2));
    const int rem = bid - n * (G2_CNT * (D_OUT / 2));
    const int g2  = rem / (D_OUT / 2);
    const int k   = rem - g2 * (D_OUT / 2);       // 0..4
    const int c1  = (2 * k) * G2_CNT + g2;
    const int c2  = c1 + G2_CNT;

    const int tid   = threadIdx.x;
    const int plane = tid >> 7;                   // 0: c1, 1: c2
    const int t     = tid & 127;                  // thread within plane
    const int wid   = t >> 5;                     // warp within plane (0..3)
    const int lane  = t & 31;

    float* __restrict__ Pb = P + plane * PLANE_F;
    const int my_c = plane ? c2 : c1;
    const float* __restrict__ src =
        feature + ((size_t)(n * C_CH + my_c)) * (H_DIM * W_DIM);

    // Zero pads: row 0 (cols 0..64) and col 0 (rows 1..64) of my plane
    if (t < IHP) Pb[t] = 0.f;                         // row 0
    if (t >= 64 && t < 128) Pb[(t - 63) * P_STRIDE] = 0.f;  // col 0, rows 1..64

    // Row scan: warp wid handles rows wid*16 .. wid*16+15 (feature rows).
    // Lane loads float2 = feature cols (2l, 2l+1); Kogge-Stone on pair sums.
    #pragma unroll
    for (int i = 0; i < 16; ++i) {
        const int frow = wid * 16 + i;            // 0..63
        const float2 v = *(const float2*)(src + frow * W_DIM + 2 * lane);
        const float pair = v.x + v.y;
        float inc = pair;
        #pragma unroll
        for (int d = 1; d < 32; d <<= 1) {
            const float up = __shfl_up_sync(0xFFFFFFFFu, inc, d);
            if (lane >= d) inc += up;
        }
        const float excl = inc - pair;
        const float o1 = excl + v.x;
        const float o2 = o1 + v.y;
        float* rp = Pb + (frow + 1) * P_STRIDE;
        rp[2 * lane + 1] = o1;
        rp[2 * lane + 2] = o2;
    }
    __syncthreads();

    // Column scan (segmented): col = (t&63)+1, seg = t>>6 -> rows seg*32+1..+32
    {
        const int col = (t & 63) + 1;
        const int r0  = (t >> 6) * 32 + 1;
        float s = 0.f;
        #pragma unroll
        for (int kk = 0; kk < 32; ++kk) {
            float* p = Pb + (r0 + kk) * P_STRIDE + col;
            s += *p;
            *p = s;
        }
    }
    __syncthreads();

    // Fixup: add top-segment column total to rows 33..64.
    // 128 threads: col = (t&63)+1, half = t>>6 -> rows 33+16*half .. 48+16*half
    {
        const int col = (t & 63) + 1;
        const int r0  = 33 + (t >> 6) * 16;
        const float off = Pb[32 * P_STRIDE + col];
        #pragma unroll
        for (int kk = 0; kk < 16; ++kk) {
            Pb[(r0 + kk) * P_STRIDE + col] += off;
        }
    }
    __syncthreads();

    // Pooling: all 256 threads; one bounds load serves both planes.
    const float* __restrict__ A = P;
    const float* __restrict__ B = P + PLANE_F;
    const int s_idx = g_batch_start[n];
    const int e_idx = g_batch_start[n + 1];

    for (int i = s_idx + tid; i < e_idx; i += 256) {
        const int r = g_roi_sorted[i];
        const uint32_t pk = g_bounds[r * G2_CNT + g2];
        const int hs = (int)(pk & 0xFF);
        const int he = (int)((pk >> 8) & 0xFF);
        const int ws = (int)((pk >> 16) & 0xFF);
        const int we = (int)(pk >> 24);

        const int o00 = he * P_STRIDE + we;
        const int o01 = hs * P_STRIDE + we;
        const int o10 = he * P_STRIDE + ws;
        const int o11 = hs * P_STRIDE + ws;

        const float sA = ((A[o00] - A[o01]) - A[o10]) + A[o11];
        const float sB = ((B[o00] - B[o01]) - B[o10]) + B[o11];

        const int area = (he - hs) * (we - ws);
        const float inv_area = 1.0f / fmaxf((float)area, 1.0f);
        const bool empty = (area <= 0);

        float* op = out + (size_t)r * C_CH;
        op[c1] = empty ? 0.f : sA * inv_area;
        op[c2] = empty ? 0.f : sB * inv_area;
    }
}

extern "C" void kernel_launch(void* const* d_in, const int* in_sizes, int n_in,
                              void* d_out, int out_size) {
    const float* feature = (const float*)d_in[0];   // (8, 490, 64, 64) fp32
    const float* rois    = (const float*)d_in[1];   // (2000, 5) fp32
    float* out = (float*)d_out;                     // (2000, 10, 7, 7) fp32

    const int bounds_blocks = (R_ROIS * G2_CNT + 255) / 256;   // 383
    prep_kernel<<<1 + bounds_blocks, 256>>>(rois);
    fused_kernel<<<N_BATCH * G2_CNT * (D_OUT / 2), 256>>>(feature, out);
}